// round 2
// baseline (speedup 1.0000x reference)
#include <cuda_runtime.h>
#include <math.h>

#define N_NODES 20000
#define N_EDGES 320000
#define T_STEPS 16
#define HG 64
#define HT 128
#define G3 384
#define LN_EPS 1e-5f

// ------------------------- scratch (static device globals) -------------------
__device__ int   g_cnt[N_NODES];
__device__ int   g_fill[N_NODES];
__device__ int   g_rowptr[N_NODES + 1];
__device__ int   g_col[N_EDGES];
__device__ float g_h0[N_NODES * HG];     // layer-0 output
__device__ float g_agg[N_NODES * HG];    // layer-1 aggregated neighbors
__device__ float g_H[N_NODES * HG];      // stack output (GRU input)
__device__ float g_gi[N_NODES * G3];
__device__ float g_gh[N_NODES * G3];
__device__ float g_hid[N_NODES * HT];    // GRU hidden (updated in place)

__device__ __forceinline__ float warp_sum(float v) {
#pragma unroll
    for (int o = 16; o; o >>= 1) v += __shfl_xor_sync(0xFFFFFFFFu, v, o);
    return v;
}

// ------------------------- init / CSR build ---------------------------------
__global__ void k_zero_all() {
    int idx = blockIdx.x * blockDim.x + threadIdx.x;   // grid covers N*HT
    if (idx < N_NODES * HT) g_hid[idx] = 0.f;
    if (idx < N_NODES) { g_cnt[idx] = 0; g_fill[idx] = 0; }
}

__global__ void k_hist(const int* __restrict__ ei) {
    int e = blockIdx.x * blockDim.x + threadIdx.x;
    if (e < N_EDGES) atomicAdd(&g_cnt[ei[N_EDGES + e]], 1);
}

__global__ void k_scan() {
    __shared__ int sh[1024];
    __shared__ int base;
    int tid = threadIdx.x;
    if (tid == 0) { base = 0; g_rowptr[0] = 0; }
    __syncthreads();
    for (int start = 0; start < N_NODES; start += 1024) {
        int i = start + tid;
        int v = (i < N_NODES) ? g_cnt[i] : 0;
        sh[tid] = v;
        __syncthreads();
        for (int off = 1; off < 1024; off <<= 1) {
            int t = (tid >= off) ? sh[tid - off] : 0;
            __syncthreads();
            sh[tid] += t;
            __syncthreads();
        }
        if (i < N_NODES) g_rowptr[i + 1] = base + sh[tid];
        __syncthreads();
        if (tid == 1023) base += sh[1023];
        __syncthreads();
    }
}

__global__ void k_scatter(const int* __restrict__ ei) {
    int e = blockIdx.x * blockDim.x + threadIdx.x;
    if (e >= N_EDGES) return;
    int d = ei[N_EDGES + e];
    int p = atomicAdd(&g_fill[d], 1);
    g_col[g_rowptr[d] + p] = ei[e];   // src
}

// ------------------- layer 0: scalar aggregate + SAGE + LN + relu -----------
__global__ void k_stack0(const float* __restrict__ xt,
                         const float* __restrict__ Wl, const float* __restrict__ Wr,
                         const float* __restrict__ b0,
                         const float* __restrict__ g, const float* __restrict__ beta) {
    int warp = (blockIdx.x * blockDim.x + threadIdx.x) >> 5;
    int lane = threadIdx.x & 31;
    if (warp >= N_NODES) return;
    int beg = g_rowptr[warp], end = g_rowptr[warp + 1];
    float acc = 0.f;
    for (int i = beg + lane; i < end; i += 32) acc += xt[g_col[i]];
    acc = warp_sum(acc);
    float deg = fmaxf((float)(end - beg), 1.f);
    float agg = acc / deg;
    float xv = xt[warp];
    float v0 = agg * Wl[lane]      + xv * Wr[lane]      + b0[lane];
    float v1 = agg * Wl[lane + 32] + xv * Wr[lane + 32] + b0[lane + 32];
    float mu = warp_sum(v0 + v1) * (1.f / 64.f);
    float d0 = v0 - mu, d1 = v1 - mu;
    float var = warp_sum(d0 * d0 + d1 * d1) * (1.f / 64.f);
    float inv = rsqrtf(var + LN_EPS);
    g_h0[warp * HG + lane]      = fmaxf(d0 * inv * g[lane]      + beta[lane], 0.f);
    g_h0[warp * HG + lane + 32] = fmaxf(d1 * inv * g[lane + 32] + beta[lane + 32], 0.f);
}

// ------------------- layer 1: 64-dim aggregate ------------------------------
__global__ void k_agg1() {
    int warp = (blockIdx.x * blockDim.x + threadIdx.x) >> 5;
    int lane = threadIdx.x & 31;
    if (warp >= N_NODES) return;
    int beg = g_rowptr[warp], end = g_rowptr[warp + 1];
    float a0 = 0.f, a1 = 0.f;
    for (int i = beg; i < end; i++) {
        int s = g_col[i];
        a0 += g_h0[s * HG + lane];
        a1 += g_h0[s * HG + lane + 32];
    }
    float inv = 1.f / fmaxf((float)(end - beg), 1.f);
    g_agg[warp * HG + lane]      = a0 * inv;
    g_agg[warp * HG + lane + 32] = a1 * inv;
}

// ------------------- layer 1: SAGE matmul + LN + relu -----------------------
// 16 nodes per block, 8 warps; each warp handles 2 nodes (register-reused W).
// smem: 32KB weights + 8KB inputs = 40KB.
__global__ void k_sage1(const float* __restrict__ Wl, const float* __restrict__ Wr,
                        const float* __restrict__ b1,
                        const float* __restrict__ g, const float* __restrict__ beta) {
    __shared__ float Ws[128 * 64];     // [k][j], k<64: Wl, k>=64: Wr
    __shared__ float ins[16][128];     // per node: [agg(64) | h0(64)]
    int tid = threadIdx.x;             // 256
    for (int i = tid; i < 64 * 64; i += 256) {
        Ws[i] = Wl[i];                 // rows 0..63
        Ws[64 * 64 + i] = Wr[i];       // rows 64..127
    }
    int nodeBase = blockIdx.x * 16;
    for (int i = tid; i < 16 * 64; i += 256) {
        int nl = i >> 6, j = i & 63;
        int n = nodeBase + nl;
        float a = 0.f, h = 0.f;
        if (n < N_NODES) { a = g_agg[n * HG + j]; h = g_h0[n * HG + j]; }
        ins[nl][j] = a;
        ins[nl][64 + j] = h;
    }
    __syncthreads();
    int warp = tid >> 5, lane = tid & 31;
    float acc0[2], acc1[2];
#pragma unroll
    for (int r = 0; r < 2; r++) { acc0[r] = b1[lane]; acc1[r] = b1[lane + 32]; }
#pragma unroll 4
    for (int k = 0; k < 128; k++) {
        float w0 = Ws[k * 64 + lane];
        float w1 = Ws[k * 64 + lane + 32];
#pragma unroll
        for (int r = 0; r < 2; r++) {
            float in = ins[warp * 2 + r][k];
            acc0[r] += in * w0;
            acc1[r] += in * w1;
        }
    }
#pragma unroll
    for (int r = 0; r < 2; r++) {
        int n = nodeBase + warp * 2 + r;
        if (n >= N_NODES) continue;
        float v0 = acc0[r], v1 = acc1[r];
        float mu = warp_sum(v0 + v1) * (1.f / 64.f);
        float d0 = v0 - mu, d1 = v1 - mu;
        float var = warp_sum(d0 * d0 + d1 * d1) * (1.f / 64.f);
        float inv = rsqrtf(var + LN_EPS);
        g_H[n * HG + lane]      = fmaxf(d0 * inv * g[lane]      + beta[lane], 0.f);
        g_H[n * HG + lane + 32] = fmaxf(d1 * inv * g[lane + 32] + beta[lane + 32], 0.f);
    }
}

// ------------------- GEMM: C = A(NxK) * W^T(384xK) + bias -------------------
// MODE 0: g_gi = g_H   @ Wih^T  (K=64)
// MODE 1: g_gh = g_hid @ Whh^T  (K=128)
// Buffers are referenced as device globals IN DEVICE CODE (host code must
// never pass __device__ symbols as args — on GB300/ATS that silently targets
// the host shadow copy).
#define BM 64
#define BN 64
#define BKK 16
template <int MODE>
__global__ void k_gemm_bias(const float* __restrict__ W, const float* __restrict__ bias) {
    constexpr int K = (MODE == 0) ? HG : HT;
    constexpr int M = G3;
    const float* __restrict__ A = (MODE == 0) ? g_H : g_hid;
    float* __restrict__ C       = (MODE == 0) ? g_gi : g_gh;

    __shared__ float As[BM][BKK + 1];
    __shared__ float Bs[BN][BKK + 1];
    int tid = threadIdx.x;            // 256
    int tx = tid & 15, ty = tid >> 4;
    int rowBase = blockIdx.y * BM;
    int colBase = blockIdx.x * BN;
    float acc[4][4] = {};
#pragma unroll
    for (int k0 = 0; k0 < K; k0 += BKK) {
#pragma unroll
        for (int i = 0; i < 4; i++) {
            int idx = tid + i * 256;            // 0..1023
            int r = idx >> 4, c = idx & 15;
            int gr = rowBase + r;
            As[r][c] = (gr < N_NODES) ? A[gr * K + k0 + c] : 0.f;
            Bs[r][c] = W[(colBase + r) * K + k0 + c];
        }
        __syncthreads();
#pragma unroll
        for (int kk = 0; kk < BKK; kk++) {
            float a[4], b[4];
#pragma unroll
            for (int i = 0; i < 4; i++) a[i] = As[ty * 4 + i][kk];
#pragma unroll
            for (int j = 0; j < 4; j++) b[j] = Bs[tx * 4 + j][kk];
#pragma unroll
            for (int i = 0; i < 4; i++)
#pragma unroll
                for (int j = 0; j < 4; j++) acc[i][j] += a[i] * b[j];
        }
        __syncthreads();
    }
#pragma unroll
    for (int i = 0; i < 4; i++) {
        int r = rowBase + ty * 4 + i;
        if (r < N_NODES) {
#pragma unroll
            for (int j = 0; j < 4; j++) {
                int c = colBase + tx * 4 + j;
                C[r * M + c] = acc[i][j] + bias[c];
            }
        }
    }
}

// ------------------- GRU gate fusion (in-place hidden update) ---------------
__global__ void k_gates() {
    int idx = blockIdx.x * blockDim.x + threadIdx.x;
    if (idx >= N_NODES * HT) return;
    int n = idx >> 7, j = idx & 127;
    const float* gi = g_gi + n * G3;
    const float* gh = g_gh + n * G3;
    float ir = gi[j], iz = gi[128 + j], in_ = gi[256 + j];
    float hr = gh[j], hz = gh[128 + j], hn = gh[256 + j];
    float r = 1.f / (1.f + expf(-(ir + hr)));
    float z = 1.f / (1.f + expf(-(iz + hz)));
    float nn = tanhf(in_ + r * hn);
    float h = g_hid[idx];
    g_hid[idx] = (1.f - z) * nn + z * h;
}

// ------------------- output head --------------------------------------------
__global__ void k_head(const float* __restrict__ W, const float* __restrict__ b,
                       float* __restrict__ y) {
    int warp = (blockIdx.x * blockDim.x + threadIdx.x) >> 5;
    int lane = threadIdx.x & 31;
    if (warp >= N_NODES) return;
    float acc = 0.f;
#pragma unroll
    for (int i = 0; i < 4; i++) {
        int j = lane + 32 * i;
        acc += g_hid[warp * HT + j] * W[j];
    }
    acc = warp_sum(acc);
    if (lane == 0) y[warp] = acc + b[0];
}

// ------------------------- launch -------------------------------------------
extern "C" void kernel_launch(void* const* d_in, const int* in_sizes, int n_in,
                              void* d_out, int out_size) {
    const float* x_seq = (const float*)d_in[0];   // (1, T, N, 1)
    const int*   ei    = (const int*)d_in[1];     // (2, E)
    const float* W_l0  = (const float*)d_in[2];
    const float* W_r0  = (const float*)d_in[3];
    const float* b0    = (const float*)d_in[4];
    const float* ln0g  = (const float*)d_in[5];
    const float* ln0b  = (const float*)d_in[6];
    const float* W_l1  = (const float*)d_in[7];
    const float* W_r1  = (const float*)d_in[8];
    const float* b1    = (const float*)d_in[9];
    const float* ln1g  = (const float*)d_in[10];
    const float* ln1b  = (const float*)d_in[11];
    const float* Wih   = (const float*)d_in[12];  // (384, 64)
    const float* Whh   = (const float*)d_in[13];  // (384, 128)
    const float* bih   = (const float*)d_in[14];
    const float* bhh   = (const float*)d_in[15];
    const float* headW = (const float*)d_in[16];
    const float* headb = (const float*)d_in[17];
    float* y = (float*)d_out;

    // init + CSR build
    k_zero_all<<<(N_NODES * HT + 255) / 256, 256>>>();
    k_hist<<<(N_EDGES + 255) / 256, 256>>>(ei);
    k_scan<<<1, 1024>>>();
    k_scatter<<<(N_EDGES + 255) / 256, 256>>>(ei);

    dim3 gemm_grid(G3 / BN, (N_NODES + BM - 1) / BM);

    for (int t = 0; t < T_STEPS; t++) {
        const float* xt = x_seq + t * N_NODES;
        k_stack0<<<(N_NODES * 32 + 255) / 256, 256>>>(xt, W_l0, W_r0, b0, ln0g, ln0b);
        k_agg1<<<(N_NODES * 32 + 255) / 256, 256>>>();
        k_sage1<<<(N_NODES + 15) / 16, 256>>>(W_l1, W_r1, b1, ln1g, ln1b);
        k_gemm_bias<0><<<gemm_grid, 256>>>(Wih, bih);
        k_gemm_bias<1><<<gemm_grid, 256>>>(Whh, bhh);
        k_gates<<<(N_NODES * HT + 255) / 256, 256>>>();
    }
    k_head<<<(N_NODES * 32 + 255) / 256, 256>>>(headW, headb, y);
}

// round 3
// speedup vs baseline: 1.2787x; 1.2787x over previous
#include <cuda_runtime.h>
#include <math.h>

#define N_NODES 20000
#define N_EDGES 320000
#define T_STEPS 16
#define HG 64
#define HT 128
#define G3 384
#define NT (N_NODES * T_STEPS)
#define LN_EPS 1e-5f

// ------------------------- scratch (static device globals) -------------------
__device__ int   g_cnt[N_NODES];
__device__ int   g_fill[N_NODES];
__device__ int   g_rowptr[N_NODES + 1];
__device__ int   g_col[N_EDGES];
__device__ float g_ws1[HG * 2 * HG];        // stacked [Wl1;Wr1] as (M=64, K=128) row-major
__device__ float g_h0_all[NT * HG];         // layer-0 output, t-major: [t][n][j]
__device__ float g_ins_all[NT * (2 * HG)];  // sage1 input rows: [agg(64) | h0(64)]
__device__ float g_S_all[NT * HG];          // sage1 raw (pre-LN)
__device__ float g_H_all[NT * HG];          // stack output (GRU input), all t
__device__ float g_gi_all[NT * G3];         // input gates, all t
__device__ float g_gh[N_NODES * G3];        // hidden gates (per step)
__device__ float g_hid[N_NODES * HT];       // GRU hidden (updated in place)

__device__ __forceinline__ float warp_sum(float v) {
#pragma unroll
    for (int o = 16; o; o >>= 1) v += __shfl_xor_sync(0xFFFFFFFFu, v, o);
    return v;
}

// ------------------------- init / CSR build ---------------------------------
__global__ void k_zero_all() {
    int idx = blockIdx.x * blockDim.x + threadIdx.x;
    if (idx < N_NODES * HT) g_hid[idx] = 0.f;
    if (idx < N_NODES) { g_cnt[idx] = 0; g_fill[idx] = 0; }
}

__global__ void k_hist(const int* __restrict__ ei) {
    int e = blockIdx.x * blockDim.x + threadIdx.x;
    if (e < N_EDGES) atomicAdd(&g_cnt[ei[N_EDGES + e]], 1);
}

__global__ void k_scan() {
    __shared__ int sh[1024];
    __shared__ int base;
    int tid = threadIdx.x;
    if (tid == 0) { base = 0; g_rowptr[0] = 0; }
    __syncthreads();
    for (int start = 0; start < N_NODES; start += 1024) {
        int i = start + tid;
        int v = (i < N_NODES) ? g_cnt[i] : 0;
        sh[tid] = v;
        __syncthreads();
        for (int off = 1; off < 1024; off <<= 1) {
            int t = (tid >= off) ? sh[tid - off] : 0;
            __syncthreads();
            sh[tid] += t;
            __syncthreads();
        }
        if (i < N_NODES) g_rowptr[i + 1] = base + sh[tid];
        __syncthreads();
        if (tid == 1023) base += sh[1023];
        __syncthreads();
    }
}

__global__ void k_scatter(const int* __restrict__ ei) {
    int e = blockIdx.x * blockDim.x + threadIdx.x;
    if (e >= N_EDGES) return;
    int d = ei[N_EDGES + e];
    int p = atomicAdd(&g_fill[d], 1);
    g_col[g_rowptr[d] + p] = ei[e];   // src
}

// Build stacked sage1 weight: g_ws1[m][k] = k<64 ? Wl1[k][m] : Wr1[k-64][m]
__global__ void k_prep_ws1(const float* __restrict__ Wl1, const float* __restrict__ Wr1) {
    int idx = blockIdx.x * blockDim.x + threadIdx.x;
    if (idx >= HG * 2 * HG) return;
    int m = idx >> 7, k = idx & 127;
    g_ws1[idx] = (k < HG) ? Wl1[k * HG + m] : Wr1[(k - HG) * HG + m];
}

// ------------------- layer 0 (batched over all t): agg + SAGE + LN + relu ---
// grid: (2500, T), 256 threads; warp per node within timestep blockIdx.y.
__global__ void k_stack0_all(const float* __restrict__ x_seq,
                             const float* __restrict__ Wl, const float* __restrict__ Wr,
                             const float* __restrict__ b0,
                             const float* __restrict__ g, const float* __restrict__ beta) {
    int t = blockIdx.y;
    int n = blockIdx.x * 8 + (threadIdx.x >> 5);
    int lane = threadIdx.x & 31;
    if (n >= N_NODES) return;
    const float* xt = x_seq + t * N_NODES;
    int beg = g_rowptr[n], end = g_rowptr[n + 1];
    float acc = 0.f;
    for (int i = beg + lane; i < end; i += 32) acc += xt[g_col[i]];
    acc = warp_sum(acc);
    float deg = fmaxf((float)(end - beg), 1.f);
    float agg = acc / deg;
    float xv = xt[n];
    float v0 = agg * Wl[lane]      + xv * Wr[lane]      + b0[lane];
    float v1 = agg * Wl[lane + 32] + xv * Wr[lane + 32] + b0[lane + 32];
    float mu = warp_sum(v0 + v1) * (1.f / 64.f);
    float d0 = v0 - mu, d1 = v1 - mu;
    float var = warp_sum(d0 * d0 + d1 * d1) * (1.f / 64.f);
    float inv = rsqrtf(var + LN_EPS);
    float h0a = fmaxf(d0 * inv * g[lane]      + beta[lane], 0.f);
    float h0b = fmaxf(d1 * inv * g[lane + 32] + beta[lane + 32], 0.f);
    long row = (long)t * N_NODES + n;
    g_h0_all[row * HG + lane]      = h0a;
    g_h0_all[row * HG + lane + 32] = h0b;
    g_ins_all[row * 128 + 64 + lane]      = h0a;
    g_ins_all[row * 128 + 64 + lane + 32] = h0b;
}

// ------------------- layer 1 aggregate (batched over all t) -----------------
__global__ void k_agg1_all() {
    int t = blockIdx.y;
    int n = blockIdx.x * 8 + (threadIdx.x >> 5);
    int lane = threadIdx.x & 31;
    if (n >= N_NODES) return;
    const float* h0t = g_h0_all + (long)t * N_NODES * HG;
    int beg = g_rowptr[n], end = g_rowptr[n + 1];
    float a0 = 0.f, a1 = 0.f;
    for (int i = beg; i < end; i++) {
        int s = g_col[i];
        a0 += h0t[s * HG + lane];
        a1 += h0t[s * HG + lane + 32];
    }
    float inv = 1.f / fmaxf((float)(end - beg), 1.f);
    long row = (long)t * N_NODES + n;
    g_ins_all[row * 128 + lane]      = a0 * inv;
    g_ins_all[row * 128 + lane + 32] = a1 * inv;
}

// ------------------- generic SGEMM: C = A(rows x K) * W^T(M x K) + bias -----
// MODE 0: S_all  = ins_all @ ws1^T  (rows=NT, K=128, M=64)
// MODE 1: gi_all = H_all   @ Wih^T  (rows=NT, K=64,  M=384)
// MODE 2: gh     = hid     @ Whh^T  (rows=N,  K=128, M=384)
// Buffers referenced as device globals in DEVICE code only (GB300/ATS trap:
// passing __device__ symbols from host silently hits the host shadow).
#define PADF 4
template <int MODE>
__global__ void k_gemm(const float* __restrict__ W, const float* __restrict__ bias) {
    constexpr int K    = (MODE == 1) ? 64 : 128;
    constexpr int M    = (MODE == 0) ? 64 : 384;
    constexpr int ROWS = (MODE == 2) ? N_NODES : NT;
    constexpr int BM = 128;
    constexpr int BN = (MODE == 0) ? 64 : 128;
    constexpr int BK = 16;
    constexpr int TM = 8;
    constexpr int TN = (MODE == 0) ? 4 : 8;
    const float* __restrict__ A = (MODE == 0) ? g_ins_all : (MODE == 1) ? g_H_all : g_hid;
    float* __restrict__ C       = (MODE == 0) ? g_S_all   : (MODE == 1) ? g_gi_all : g_gh;
    const float* Wm = (MODE == 0) ? g_ws1 : W;

    __shared__ float As[BK][BM + PADF];
    __shared__ float Bs[BK][BN + PADF];

    int tid = threadIdx.x;               // 256
    int tx = tid & 15, ty = tid >> 4;    // 16 x 16
    int rowBase = blockIdx.y * BM;
    int colBase = blockIdx.x * BN;

    float acc[TM][TN];
#pragma unroll
    for (int i = 0; i < TM; i++)
#pragma unroll
        for (int j = 0; j < TN; j++) acc[i][j] = 0.f;

#pragma unroll
    for (int k0 = 0; k0 < K; k0 += BK) {
        // load A tile (BM x BK), transposed into As[k][m]
#pragma unroll
        for (int v = 0; v < (BM * BK) / (4 * 256); v++) {
            int f4 = tid + v * 256;                // over BM*BK/4
            int r = f4 >> 2;
            int c = (f4 & 3) * 4;
            int gr = rowBase + r;
            float4 val = make_float4(0.f, 0.f, 0.f, 0.f);
            if (gr < ROWS) val = *(const float4*)(A + (long)gr * K + k0 + c);
            As[c + 0][r] = val.x;
            As[c + 1][r] = val.y;
            As[c + 2][r] = val.z;
            As[c + 3][r] = val.w;
        }
        // load B tile (BN x BK), transposed into Bs[k][n]
#pragma unroll
        for (int v = 0; v < (BN * BK) / (4 * 256); v++) {
            int f4 = tid + v * 256;
            int n = f4 >> 2;
            int c = (f4 & 3) * 4;
            float4 val = *(const float4*)(Wm + (long)(colBase + n) * K + k0 + c);
            Bs[c + 0][n] = val.x;
            Bs[c + 1][n] = val.y;
            Bs[c + 2][n] = val.z;
            Bs[c + 3][n] = val.w;
        }
        __syncthreads();
#pragma unroll
        for (int kk = 0; kk < BK; kk++) {
            float a[TM], b[TN];
            *(float4*)(a)     = *(const float4*)(&As[kk][ty * TM]);
            *(float4*)(a + 4) = *(const float4*)(&As[kk][ty * TM + 4]);
            *(float4*)(b)     = *(const float4*)(&Bs[kk][tx * TN]);
            if (TN == 8) *(float4*)(b + 4) = *(const float4*)(&Bs[kk][tx * TN + 4]);
#pragma unroll
            for (int i = 0; i < TM; i++)
#pragma unroll
                for (int j = 0; j < TN; j++) acc[i][j] += a[i] * b[j];
        }
        __syncthreads();
    }
#pragma unroll
    for (int i = 0; i < TM; i++) {
        int r = rowBase + ty * TM + i;
        if (r < ROWS) {
#pragma unroll
            for (int j = 0; j < TN; j++) {
                int c = colBase + tx * TN + j;
                C[(long)r * M + c] = acc[i][j] + bias[c];
            }
        }
    }
}

// ------------------- sage1 LN + relu (batched) -------------------------------
__global__ void k_ln1(const float* __restrict__ g, const float* __restrict__ beta) {
    long row = (long)((blockIdx.x * blockDim.x + threadIdx.x) >> 5);
    int lane = threadIdx.x & 31;
    if (row >= NT) return;
    float v0 = g_S_all[row * HG + lane];
    float v1 = g_S_all[row * HG + lane + 32];
    float mu = warp_sum(v0 + v1) * (1.f / 64.f);
    float d0 = v0 - mu, d1 = v1 - mu;
    float var = warp_sum(d0 * d0 + d1 * d1) * (1.f / 64.f);
    float inv = rsqrtf(var + LN_EPS);
    g_H_all[row * HG + lane]      = fmaxf(d0 * inv * g[lane]      + beta[lane], 0.f);
    g_H_all[row * HG + lane + 32] = fmaxf(d1 * inv * g[lane + 32] + beta[lane + 32], 0.f);
}

// ------------------- GRU gate fusion (in-place hidden update) ---------------
__global__ void k_gates(int t) {
    int idx = blockIdx.x * blockDim.x + threadIdx.x;
    if (idx >= N_NODES * HT) return;
    int n = idx >> 7, j = idx & 127;
    const float* gi = g_gi_all + ((long)t * N_NODES + n) * G3;
    const float* gh = g_gh + (long)n * G3;
    float ir = gi[j], iz = gi[128 + j], in_ = gi[256 + j];
    float hr = gh[j], hz = gh[128 + j], hn = gh[256 + j];
    float r = 1.f / (1.f + expf(-(ir + hr)));
    float z = 1.f / (1.f + expf(-(iz + hz)));
    float nn = tanhf(in_ + r * hn);
    float h = g_hid[idx];
    g_hid[idx] = (1.f - z) * nn + z * h;
}

// ------------------- output head --------------------------------------------
__global__ void k_head(const float* __restrict__ W, const float* __restrict__ b,
                       float* __restrict__ y) {
    int warp = (blockIdx.x * blockDim.x + threadIdx.x) >> 5;
    int lane = threadIdx.x & 31;
    if (warp >= N_NODES) return;
    float acc = 0.f;
#pragma unroll
    for (int i = 0; i < 4; i++) {
        int j = lane + 32 * i;
        acc += g_hid[warp * HT + j] * W[j];
    }
    acc = warp_sum(acc);
    if (lane == 0) y[warp] = acc + b[0];
}

// ------------------------- launch -------------------------------------------
extern "C" void kernel_launch(void* const* d_in, const int* in_sizes, int n_in,
                              void* d_out, int out_size) {
    const float* x_seq = (const float*)d_in[0];   // (1, T, N, 1)
    const int*   ei    = (const int*)d_in[1];     // (2, E)
    const float* W_l0  = (const float*)d_in[2];
    const float* W_r0  = (const float*)d_in[3];
    const float* b0    = (const float*)d_in[4];
    const float* ln0g  = (const float*)d_in[5];
    const float* ln0b  = (const float*)d_in[6];
    const float* W_l1  = (const float*)d_in[7];
    const float* W_r1  = (const float*)d_in[8];
    const float* b1    = (const float*)d_in[9];
    const float* ln1g  = (const float*)d_in[10];
    const float* ln1b  = (const float*)d_in[11];
    const float* Wih   = (const float*)d_in[12];  // (384, 64)
    const float* Whh   = (const float*)d_in[13];  // (384, 128)
    const float* bih   = (const float*)d_in[14];
    const float* bhh   = (const float*)d_in[15];
    const float* headW = (const float*)d_in[16];
    const float* headb = (const float*)d_in[17];
    float* y = (float*)d_out;

    // init + CSR build + weight prep
    k_zero_all<<<(N_NODES * HT + 255) / 256, 256>>>();
    k_hist<<<(N_EDGES + 255) / 256, 256>>>(ei);
    k_scan<<<1, 1024>>>();
    k_scatter<<<(N_EDGES + 255) / 256, 256>>>(ei);
    k_prep_ws1<<<(HG * 2 * HG + 255) / 256, 256>>>(W_l1, W_r1);

    // phase A: all timesteps batched
    dim3 gridA((N_NODES + 7) / 8, T_STEPS);
    k_stack0_all<<<gridA, 256>>>(x_seq, W_l0, W_r0, b0, ln0g, ln0b);
    k_agg1_all<<<gridA, 256>>>();

    dim3 grid_s1(HG / 64, (NT + 127) / 128);              // (1, 2500)
    k_gemm<0><<<grid_s1, 256>>>(nullptr, b1);
    k_ln1<<<(NT * 32 + 255) / 256, 256>>>(ln1g, ln1b);

    dim3 grid_gi(G3 / 128, (NT + 127) / 128);             // (3, 2500)
    k_gemm<1><<<grid_gi, 256>>>(Wih, bih);

    // phase B: sequential GRU
    dim3 grid_gh(G3 / 128, (N_NODES + 127) / 128);        // (3, 157)
    for (int t = 0; t < T_STEPS; t++) {
        k_gemm<2><<<grid_gh, 256>>>(Whh, bhh);
        k_gates<<<(N_NODES * HT + 255) / 256, 256>>>(t);
    }
    k_head<<<(N_NODES * 32 + 255) / 256, 256>>>(headW, headb, y);
}

// round 5
// speedup vs baseline: 1.7956x; 1.4043x over previous
#include <cuda_runtime.h>
#include <math.h>
#include <stdint.h>

#define N_NODES 20000
#define N_EDGES 320000
#define T_STEPS 16
#define HG 64
#define HT 128
#define G3 384
#define NT (N_NODES * T_STEPS)
#define LN_EPS 1e-5f

// ===================== scratch (static device globals) =======================
__device__ int   g_cnt[N_NODES];
__device__ int   g_fill[N_NODES];
__device__ int   g_rowptr[N_NODES + 1];
__device__ int   g_col[N_EDGES];
__device__ float g_ws1[HG * 2 * HG];        // stacked [Wl1;Wr1]: (out=64, K=128)
__device__ float g_h0_all[NT * HG];
__device__ float g_ins_all[NT * (2 * HG)];  // sage1 input: [agg(64) | h0(64)]
__device__ float g_H_all[NT * HG];
__device__ float g_gi_all[NT * G3];
__device__ float g_hid[N_NODES * HT];

__device__ __forceinline__ float warp_sum(float v) {
#pragma unroll
    for (int o = 16; o; o >>= 1) v += __shfl_xor_sync(0xFFFFFFFFu, v, o);
    return v;
}

// tf32 convert (round-to-nearest), result kept as float bit-pattern
__device__ __forceinline__ float f2tf(float x) {
    uint32_t u;
    asm("cvt.rna.tf32.f32 %0, %1;" : "=r"(u) : "f"(x));
    return __uint_as_float(u);
}

// m16n8k8 tf32 MMA (sm_80+ generic PTX — compiles at compute_103)
__device__ __forceinline__ void mma8(float* d, const uint32_t* a, uint32_t b0, uint32_t b1) {
    asm volatile(
        "mma.sync.aligned.m16n8k8.row.col.f32.tf32.tf32.f32 "
        "{%0,%1,%2,%3}, {%4,%5,%6,%7}, {%8,%9}, {%0,%1,%2,%3};"
        : "+f"(d[0]), "+f"(d[1]), "+f"(d[2]), "+f"(d[3])
        : "r"(a[0]), "r"(a[1]), "r"(a[2]), "r"(a[3]), "r"(b0), "r"(b1));
}

// ------------------------- init / CSR build ---------------------------------
__global__ void k_zero_all() {
    int idx = blockIdx.x * blockDim.x + threadIdx.x;
    if (idx < N_NODES * HT) g_hid[idx] = 0.f;
    if (idx < N_NODES) { g_cnt[idx] = 0; g_fill[idx] = 0; }
}

__global__ void k_hist(const int* __restrict__ ei) {
    int e = blockIdx.x * blockDim.x + threadIdx.x;
    if (e < N_EDGES) atomicAdd(&g_cnt[ei[N_EDGES + e]], 1);
}

__global__ void k_scan() {
    __shared__ int sh[1024];
    __shared__ int base;
    int tid = threadIdx.x;
    if (tid == 0) { base = 0; g_rowptr[0] = 0; }
    __syncthreads();
    for (int start = 0; start < N_NODES; start += 1024) {
        int i = start + tid;
        int v = (i < N_NODES) ? g_cnt[i] : 0;
        sh[tid] = v;
        __syncthreads();
        for (int off = 1; off < 1024; off <<= 1) {
            int t = (tid >= off) ? sh[tid - off] : 0;
            __syncthreads();
            sh[tid] += t;
            __syncthreads();
        }
        if (i < N_NODES) g_rowptr[i + 1] = base + sh[tid];
        __syncthreads();
        if (tid == 1023) base += sh[1023];
        __syncthreads();
    }
}

__global__ void k_scatter(const int* __restrict__ ei) {
    int e = blockIdx.x * blockDim.x + threadIdx.x;
    if (e >= N_EDGES) return;
    int d = ei[N_EDGES + e];
    int p = atomicAdd(&g_fill[d], 1);
    g_col[g_rowptr[d] + p] = ei[e];
}

__global__ void k_prep_ws1(const float* __restrict__ Wl1, const float* __restrict__ Wr1) {
    int idx = blockIdx.x * blockDim.x + threadIdx.x;
    if (idx >= HG * 2 * HG) return;
    int m = idx >> 7, k = idx & 127;
    g_ws1[idx] = (k < HG) ? Wl1[k * HG + m] : Wr1[(k - HG) * HG + m];
}

// ------------------- layer 0 (batched): agg + SAGE + LN + relu --------------
__global__ void k_stack0_all(const float* __restrict__ x_seq,
                             const float* __restrict__ Wl, const float* __restrict__ Wr,
                             const float* __restrict__ b0,
                             const float* __restrict__ g, const float* __restrict__ beta) {
    int t = blockIdx.y;
    int n = blockIdx.x * 8 + (threadIdx.x >> 5);
    int lane = threadIdx.x & 31;
    if (n >= N_NODES) return;
    const float* xt = x_seq + t * N_NODES;
    int beg = g_rowptr[n], end = g_rowptr[n + 1];
    float acc = 0.f;
    for (int i = beg + lane; i < end; i += 32) acc += xt[g_col[i]];
    acc = warp_sum(acc);
    float deg = fmaxf((float)(end - beg), 1.f);
    float agg = acc / deg;
    float xv = xt[n];
    float v0 = agg * Wl[lane]      + xv * Wr[lane]      + b0[lane];
    float v1 = agg * Wl[lane + 32] + xv * Wr[lane + 32] + b0[lane + 32];
    float mu = warp_sum(v0 + v1) * (1.f / 64.f);
    float d0 = v0 - mu, d1 = v1 - mu;
    float var = warp_sum(d0 * d0 + d1 * d1) * (1.f / 64.f);
    float inv = rsqrtf(var + LN_EPS);
    float h0a = fmaxf(d0 * inv * g[lane]      + beta[lane], 0.f);
    float h0b = fmaxf(d1 * inv * g[lane + 32] + beta[lane + 32], 0.f);
    size_t row = (size_t)t * N_NODES + n;
    g_h0_all[row * HG + lane]      = h0a;
    g_h0_all[row * HG + lane + 32] = h0b;
    g_ins_all[row * 128 + 64 + lane]      = h0a;
    g_ins_all[row * 128 + 64 + lane + 32] = h0b;
}

// ------------------- layer 1 aggregate (batched) -----------------------------
__global__ void k_agg1_all() {
    int t = blockIdx.y;
    int n = blockIdx.x * 8 + (threadIdx.x >> 5);
    int lane = threadIdx.x & 31;
    if (n >= N_NODES) return;
    const float* h0t = g_h0_all + (size_t)t * N_NODES * HG;
    int beg = g_rowptr[n], end = g_rowptr[n + 1];
    float a0 = 0.f, a1 = 0.f;
    for (int i = beg; i < end; i++) {
        int s = g_col[i];
        a0 += h0t[s * HG + lane];
        a1 += h0t[s * HG + lane + 32];
    }
    float inv = 1.f / fmaxf((float)(end - beg), 1.f);
    size_t row = (size_t)t * N_NODES + n;
    g_ins_all[row * 128 + lane]      = a0 * inv;
    g_ins_all[row * 128 + lane + 32] = a1 * inv;
}

// ===================== tf32 mma.sync GEMM kernels =============================
// MODE 0: S = ins_all(NTx128) @ ws1^T(64x128);  epilogue: +b1, LN, relu -> g_H_all
// MODE 1: gi = H_all(NTx64) @ Wih^T(384x64);    epilogue: +bih -> g_gi_all
// MODE 2: gh = hid(Nx128) @ Whh^T(384x128);     epilogue: fused GRU -> g_hid
template <int MODE>
__global__ void __launch_bounds__(256, 1)
k_mma(const float* __restrict__ Wg, const float* __restrict__ bias,
      const float* __restrict__ p0, const float* __restrict__ p1, int t) {
    constexpr int K       = (MODE == 1) ? 64 : 128;
    constexpr int GATES   = (MODE == 2) ? 3 : 1;
    constexpr int BM      = 128;
    constexpr int BN      = (MODE == 1) ? 128 : 64;
    constexpr int WARPS_N = (MODE == 1) ? 4 : 2;
    constexpr int WM      = (MODE == 1) ? 64 : 32;   // BM / WARPS_M
    constexpr int WN      = 32;                      // BN / WARPS_N
    constexpr int MF      = WM / 16;
    constexpr int NF      = WN / 8;
    constexpr int LDA     = K + 4;
    constexpr int BROWS   = BN * GATES;
    constexpr int ROWS    = (MODE == 2) ? N_NODES : NT;

    extern __shared__ float sm[];
    float* As = sm;                    // BM x LDA
    float* Bs = sm + BM * LDA;         // BROWS x LDA

    const float* A  = (MODE == 0) ? g_ins_all : (MODE == 1) ? g_H_all : g_hid;
    const float* Wm = (MODE == 0) ? g_ws1 : Wg;

    int tid = threadIdx.x;
    int rowBase = blockIdx.y * BM;
    int colBase = blockIdx.x * BN;

    // ---- stage A tile (tf32-converted) ----
    for (int idx = tid; idx < BM * (K / 4); idx += 256) {
        int r = idx / (K / 4), c = (idx % (K / 4)) * 4;
        int gr = rowBase + r;
        float4 v = make_float4(0.f, 0.f, 0.f, 0.f);
        if (gr < ROWS) v = *(const float4*)(A + (size_t)gr * K + c);
        float4 w = make_float4(f2tf(v.x), f2tf(v.y), f2tf(v.z), f2tf(v.w));
        *(float4*)(As + r * LDA + c) = w;
    }
    // ---- stage B tile(s) ----
    for (int idx = tid; idx < BROWS * (K / 4); idx += 256) {
        int r = idx / (K / 4), c = (idx % (K / 4)) * 4;
        int gr;
        if (MODE == 2) { int gate = r / BN, ln = r % BN; gr = gate * HT + colBase + ln; }
        else           { gr = colBase + r; }
        float4 v = *(const float4*)(Wm + (size_t)gr * K + c);
        float4 w = make_float4(f2tf(v.x), f2tf(v.y), f2tf(v.z), f2tf(v.w));
        *(float4*)(Bs + r * LDA + c) = w;
    }
    __syncthreads();

    int warp = tid >> 5, lane = tid & 31;
    int wm = warp / WARPS_N, wn = warp % WARPS_N;
    int g = lane >> 2, tg = lane & 3;
    int m0 = wm * WM, n0 = wn * WN;

    float acc[GATES][MF][NF][4] = {};

#pragma unroll
    for (int k0 = 0; k0 < K; k0 += 8) {
        uint32_t a[MF][4];
#pragma unroll
        for (int mf = 0; mf < MF; mf++) {
            const float* ap = As + (m0 + 16 * mf + g) * LDA + k0 + tg;
            a[mf][0] = __float_as_uint(ap[0]);
            a[mf][1] = __float_as_uint(ap[8 * LDA]);
            a[mf][2] = __float_as_uint(ap[4]);
            a[mf][3] = __float_as_uint(ap[8 * LDA + 4]);
        }
#pragma unroll
        for (int gt = 0; gt < GATES; gt++) {
#pragma unroll
            for (int nf = 0; nf < NF; nf++) {
                const float* bp = Bs + (gt * BN + n0 + 8 * nf + g) * LDA + k0 + tg;
                uint32_t b0 = __float_as_uint(bp[0]);
                uint32_t b1 = __float_as_uint(bp[4]);
#pragma unroll
                for (int mf = 0; mf < MF; mf++)
                    mma8(acc[gt][mf][nf], a[mf], b0, b1);
            }
        }
    }

    if (MODE == 0) {
        // ---- +bias into smem, then fused LN+relu ----
        __syncthreads();                       // done with As/Bs
        float* S = sm;                         // 128 x 68
#pragma unroll
        for (int mf = 0; mf < MF; mf++)
#pragma unroll
            for (int nf = 0; nf < NF; nf++) {
                int r = m0 + 16 * mf + g;
                int c = n0 + 8 * nf + 2 * tg;
                S[r * 68 + c]           = acc[0][mf][nf][0] + bias[c];
                S[r * 68 + c + 1]       = acc[0][mf][nf][1] + bias[c + 1];
                S[(r + 8) * 68 + c]     = acc[0][mf][nf][2] + bias[c];
                S[(r + 8) * 68 + c + 1] = acc[0][mf][nf][3] + bias[c + 1];
            }
        __syncthreads();
#pragma unroll
        for (int i = 0; i < 16; i++) {
            int r = warp * 16 + i;
            float v0 = S[r * 68 + lane];
            float v1 = S[r * 68 + lane + 32];
            float mu = warp_sum(v0 + v1) * (1.f / 64.f);
            float d0 = v0 - mu, d1 = v1 - mu;
            float var = warp_sum(d0 * d0 + d1 * d1) * (1.f / 64.f);
            float inv = rsqrtf(var + LN_EPS);
            size_t rowg = (size_t)rowBase + r;
            g_H_all[rowg * HG + lane]      = fmaxf(d0 * inv * p0[lane]      + p1[lane], 0.f);
            g_H_all[rowg * HG + lane + 32] = fmaxf(d1 * inv * p0[lane + 32] + p1[lane + 32], 0.f);
        }
    } else if (MODE == 1) {
        // ---- +bias, store gi (NT is an exact multiple of BM: no guards) ----
#pragma unroll
        for (int mf = 0; mf < MF; mf++)
#pragma unroll
            for (int nf = 0; nf < NF; nf++) {
                size_t r = (size_t)rowBase + m0 + 16 * mf + g;
                int c = colBase + n0 + 8 * nf + 2 * tg;
                float2 w0 = make_float2(acc[0][mf][nf][0] + bias[c],
                                        acc[0][mf][nf][1] + bias[c + 1]);
                float2 w1 = make_float2(acc[0][mf][nf][2] + bias[c],
                                        acc[0][mf][nf][3] + bias[c + 1]);
                *(float2*)(g_gi_all + r * G3 + c)       = w0;
                *(float2*)(g_gi_all + (r + 8) * G3 + c) = w1;
            }
    } else {
        // ---- fused GRU gates: h = (1-z)*n + z*h ----
#pragma unroll
        for (int mf = 0; mf < MF; mf++)
#pragma unroll
            for (int nf = 0; nf < NF; nf++) {
#pragma unroll
                for (int half = 0; half < 2; half++) {
                    int node = rowBase + m0 + 16 * mf + g + half * 8;
                    if (node >= N_NODES) continue;
                    int c = colBase + n0 + 8 * nf + 2 * tg;
                    const float* gi = g_gi_all + ((size_t)t * N_NODES + node) * G3;
                    float2 gir = *(const float2*)(gi + c);
                    float2 giz = *(const float2*)(gi + 128 + c);
                    float2 gin = *(const float2*)(gi + 256 + c);
                    float hr0 = acc[0][mf][nf][half * 2 + 0] + bias[c];
                    float hr1 = acc[0][mf][nf][half * 2 + 1] + bias[c + 1];
                    float hz0 = acc[1][mf][nf][half * 2 + 0] + bias[128 + c];
                    float hz1 = acc[1][mf][nf][half * 2 + 1] + bias[128 + c + 1];
                    float hn0 = acc[2][mf][nf][half * 2 + 0] + bias[256 + c];
                    float hn1 = acc[2][mf][nf][half * 2 + 1] + bias[256 + c + 1];
                    float* hid = g_hid + (size_t)node * HT + c;
                    float2 h = *(float2*)hid;
                    float r0 = 1.f / (1.f + __expf(-(gir.x + hr0)));
                    float r1 = 1.f / (1.f + __expf(-(gir.y + hr1)));
                    float z0 = 1.f / (1.f + __expf(-(giz.x + hz0)));
                    float z1 = 1.f / (1.f + __expf(-(giz.y + hz1)));
                    float n0v = tanhf(gin.x + r0 * hn0);
                    float n1v = tanhf(gin.y + r1 * hn1);
                    h.x = (1.f - z0) * n0v + z0 * h.x;
                    h.y = (1.f - z1) * n1v + z1 * h.y;
                    *(float2*)hid = h;
                }
            }
    }
}

// ------------------- output head ---------------------------------------------
__global__ void k_head(const float* __restrict__ W, const float* __restrict__ b,
                       float* __restrict__ y) {
    int warp = (blockIdx.x * blockDim.x + threadIdx.x) >> 5;
    int lane = threadIdx.x & 31;
    if (warp >= N_NODES) return;
    float acc = 0.f;
#pragma unroll
    for (int i = 0; i < 4; i++) {
        int j = lane + 32 * i;
        acc += g_hid[warp * HT + j] * W[j];
    }
    acc = warp_sum(acc);
    if (lane == 0) y[warp] = acc + b[0];
}

// ------------------------- launch ---------------------------------------------
extern "C" void kernel_launch(void* const* d_in, const int* in_sizes, int n_in,
                              void* d_out, int out_size) {
    const float* x_seq = (const float*)d_in[0];
    const int*   ei    = (const int*)d_in[1];
    const float* W_l0  = (const float*)d_in[2];
    const float* W_r0  = (const float*)d_in[3];
    const float* b0    = (const float*)d_in[4];
    const float* ln0g  = (const float*)d_in[5];
    const float* ln0b  = (const float*)d_in[6];
    const float* W_l1  = (const float*)d_in[7];
    const float* W_r1  = (const float*)d_in[8];
    const float* b1    = (const float*)d_in[9];
    const float* ln1g  = (const float*)d_in[10];
    const float* ln1b  = (const float*)d_in[11];
    const float* Wih   = (const float*)d_in[12];
    const float* Whh   = (const float*)d_in[13];
    const float* bih   = (const float*)d_in[14];
    const float* bhh   = (const float*)d_in[15];
    const float* headW = (const float*)d_in[16];
    const float* headb = (const float*)d_in[17];
    float* y = (float*)d_out;

    const int SMEM0 = (128 * 132 + 64 * 132) * 4;        // 101376
    const int SMEM1 = (128 * 68 + 128 * 68) * 4;         //  69632
    const int SMEM2 = (128 * 132 + 192 * 132) * 4;       // 168960
    cudaFuncSetAttribute(k_mma<0>, cudaFuncAttributeMaxDynamicSharedMemorySize, SMEM0);
    cudaFuncSetAttribute(k_mma<1>, cudaFuncAttributeMaxDynamicSharedMemorySize, SMEM1);
    cudaFuncSetAttribute(k_mma<2>, cudaFuncAttributeMaxDynamicSharedMemorySize, SMEM2);

    k_zero_all<<<(N_NODES * HT + 255) / 256, 256>>>();
    k_hist<<<(N_EDGES + 255) / 256, 256>>>(ei);
    k_scan<<<1, 1024>>>();
    k_scatter<<<(N_EDGES + 255) / 256, 256>>>(ei);
    k_prep_ws1<<<(HG * 2 * HG + 255) / 256, 256>>>(W_l1, W_r1);

    dim3 gridA((N_NODES + 7) / 8, T_STEPS);
    k_stack0_all<<<gridA, 256>>>(x_seq, W_l0, W_r0, b0, ln0g, ln0b);
    k_agg1_all<<<gridA, 256>>>();

    k_mma<0><<<dim3(1, NT / 128), 256, SMEM0>>>(nullptr, b1, ln1g, ln1b, 0);
    k_mma<1><<<dim3(3, NT / 128), 256, SMEM1>>>(Wih, bih, nullptr, nullptr, 0);

    int gridGH = (N_NODES + 127) / 128;   // 157
    for (int t = 0; t < T_STEPS; t++)
        k_mma<2><<<dim3(2, gridGH), 256, SMEM2>>>(Whh, bhh, nullptr, nullptr, t);

    k_head<<<(N_NODES * 32 + 255) / 256, 256>>>(headW, headb, y);
}